// round 6
// baseline (speedup 1.0000x reference)
#include <cuda_runtime.h>
#include <cstdint>

// out[mu[k], e] += X1[m1[k], e] * X2[m2[k], e] * mult[k]
// M=9, K~100 runtime terms, ND = N*D = 2^20, fp32.
//
// R6 design: X1 in REGISTERS (9 float4/thread via direct LDG), X2 staged via
// TMA into smem. Terms grouped into 81 (mu,m1) cells; main loop is a fully
// static 9x9 unroll:  tsum = sum_cell mult*X2[m2];  acc[mu] += A[m1]*tsum.
// Per term: 1 broadcast prog LDS.64 + 1 data LDS.128 + 2 packed f32x2 FMAs.

#define M_CH    9
#define TILE    512                    // floats per channel per block
#define TILE_B  (TILE * 4)             // 2048 bytes
#define THREADS 128
#define MAXK    128

struct Smem {
    float4 sxB[M_CH * (TILE / 4)];     // 18432 B: X2 tiles only
    int2   progB[MAXK];                // per-term {off2_bytes, mult_bits}
    int    rawkey[MAXK];               // mu*9 + m1
    int    cellcnt[81];                // terms per (mu,m1) cell
    unsigned long long mbar;
};

__global__ void __launch_bounds__(THREADS, 6)
fused_kernel(const float* __restrict__ X1, const float* __restrict__ X2,
             const int* __restrict__ m1, const int* __restrict__ m2,
             const int* __restrict__ mu, const float* __restrict__ mult,
             float* __restrict__ out, int nd4, int K)
{
    __shared__ Smem s;
    const int t = threadIdx.x;
    const int base4 = blockIdx.x * (TILE / 4);
    const uint32_t mbar_addr = (uint32_t)__cvta_generic_to_shared(&s.mbar);

    // ---- phase 0: keys to smem, mbarrier init -----------------------------
    if (t < K) s.rawkey[t] = mu[t] * 9 + m1[t];
    if (t == 0) {
        asm volatile("mbarrier.init.shared.b64 [%0], %1;"
                     :: "r"(mbar_addr), "r"(1) : "memory");
        asm volatile("fence.proxy.async.shared::cta;" ::: "memory");
    }
    __syncthreads();

    // ---- phase 1: TMA stage X2 (t0); X1 -> registers; sort ----------------
    if (t == 0) {
        asm volatile("mbarrier.arrive.expect_tx.shared.b64 _, [%0], %1;"
                     :: "r"(mbar_addr), "r"((uint32_t)(M_CH * TILE_B)) : "memory");
        uint32_t dst = (uint32_t)__cvta_generic_to_shared(&s.sxB[0]);
        const char* src2 = (const char*)(X2 + (size_t)base4 * 4);
        const size_t chanstride = (size_t)nd4 * 16;
#pragma unroll
        for (int m = 0; m < M_CH; m++)
            asm volatile(
                "cp.async.bulk.shared::cta.global.mbarrier::complete_tx::bytes "
                "[%0], [%1], %2, [%3];"
                :: "r"(dst + m * TILE_B), "l"(src2 + m * chanstride),
                   "r"((uint32_t)TILE_B), "r"(mbar_addr) : "memory");
    }

    // X1 columns straight to registers (9 x LDG.128, latency hidden by setup)
    ulonglong2 A[M_CH];
    {
        const ulonglong2* __restrict__ X1u = (const ulonglong2*)X1;
#pragma unroll
        for (int m = 0; m < M_CH; m++)
            A[m] = X1u[(size_t)m * nd4 + base4 + t];
    }

    // stable rank by cell key; scatter prog entries; count per cell
    if (t < K) {
        const int mykey = s.rawkey[t];
        int r = 0;
        for (int j = 0; j < K; j++) {
            int kj = s.rawkey[j];
            r += (kj < mykey) | ((kj == mykey) & (j < t));
        }
        int2 e;
        e.x = m2[t] * TILE_B;              // X2 smem byte offset
        e.y = __float_as_int(mult[t]);
        s.progB[r] = e;
    }
    if (t < 81) {
        int c = 0;
        for (int j = 0; j < K; j++) c += (s.rawkey[j] == t);
        s.cellcnt[t] = c;
    }
    __syncthreads();

    // ---- wait for TMA -----------------------------------------------------
    asm volatile(
        "{\n\t.reg .pred P;\n\t"
        "W_%=:\n\t"
        "mbarrier.try_wait.parity.acquire.cta.shared::cta.b64 P, [%0], 0, 0x989680;\n\t"
        "@P bra.uni D_%=;\n\t"
        "bra.uni W_%=;\n\t"
        "D_%=:\n\t}"
        :: "r"(mbar_addr) : "memory");

    // ---- main loop: static 9x9 cell unroll --------------------------------
    const uint32_t bx = (uint32_t)__cvta_generic_to_shared(&s.sxB[0]) + t * 16;
    float4* __restrict__ out4 = (float4*)out;
    int kptr = 0;

#pragma unroll
    for (int m = 0; m < M_CH; m++) {
        ulonglong2 acc; acc.x = acc.y = 0ull;
#pragma unroll
        for (int m1i = 0; m1i < M_CH; m1i++) {
            const int cnt = s.cellcnt[m * 9 + m1i];    // broadcast LDS
            ulonglong2 ts; ts.x = ts.y = 0ull;
            for (int j = 0; j < cnt; j++) {            // avg ~1.2 iters
                int2 e = s.progB[kptr + j];            // broadcast LDS.64
                ulonglong2 b;
                asm("ld.shared.v2.u64 {%0, %1}, [%2];"
                    : "=l"(b.x), "=l"(b.y) : "r"(bx + e.x));
                unsigned long long c2;
                asm("mov.b64 %0, {%1, %1};" : "=l"(c2) : "r"(e.y));
                asm("fma.rn.f32x2 %0, %1, %2, %3;"
                    : "=l"(ts.x) : "l"(c2), "l"(b.x), "l"(ts.x));
                asm("fma.rn.f32x2 %0, %1, %2, %3;"
                    : "=l"(ts.y) : "l"(c2), "l"(b.y), "l"(ts.y));
            }
            kptr += cnt;
            // acc += A[m1i] * tsum   (A[m1i] is a literal register pair)
            asm("fma.rn.f32x2 %0, %1, %2, %3;"
                : "=l"(acc.x) : "l"(A[m1i].x), "l"(ts.x), "l"(acc.x));
            asm("fma.rn.f32x2 %0, %1, %2, %3;"
                : "=l"(acc.y) : "l"(A[m1i].y), "l"(ts.y), "l"(acc.y));
        }
        *(ulonglong2*)&out4[(size_t)m * nd4 + base4 + t] = acc;   // STG.128
    }
}

extern "C" void kernel_launch(void* const* d_in, const int* in_sizes, int n_in,
                              void* d_out, int out_size)
{
    const float* X1   = (const float*)d_in[0];
    const float* X2   = (const float*)d_in[1];
    const int*   m1   = (const int*)d_in[2];
    const int*   m2   = (const int*)d_in[3];
    const int*   mu   = (const int*)d_in[4];
    const float* mult = (const float*)d_in[5];
    float*       out  = (float*)d_out;

    const int K   = in_sizes[2];
    const int ND  = in_sizes[0] / M_CH;    // N*D
    const int nd4 = ND / 4;

    fused_kernel<<<ND / TILE, THREADS>>>(X1, X2, m1, m2, mu, mult, out, nd4, K);
}

// round 7
// speedup vs baseline: 3.1692x; 3.1692x over previous
#include <cuda_runtime.h>
#include <cstdint>

// out[mu[k], e] += X1[m1[k], e] * X2[m2[k], e] * mult[k]
// M=9, K~100 runtime terms (mu PRE-SORTED per reference), ND = 2^20, fp32.
//
// R7: flat-program kernel, 256 threads/block, one float2 column per thread
// (40 warps/SM at 5 CTAs).  TMA stages 18 channel tiles; setup (histogram +
// pad) hidden behind TMA; terms taken in input order (mu sorted).  Program
// packs 2 terms per int4: {off1|off2<<16, mult} x2.  Per term per warp:
// 0.5 broadcast LDS + 2+2 data LDS.64 wavefronts; packed f32x2 math.

#define M_CH    9
#define TILE    512                    // floats per channel per block
#define TILE_B  (TILE * 4)             // 2048 bytes per channel tile
#define THREADS 256
#define MAXK    128
#define PROGMAX 144                    // padded program (pairs of terms)

struct Smem {
    float2 sx[2 * M_CH * (TILE / 2)];  // 36864 B: X1 tiles then X2 tiles
    int2   prog[PROGMAX];              // {off1|off2<<16, mult_bits} per term
    int    rawmu[MAXK];
    int    seg[M_CH + 1];
    int    pseg[M_CH + 1];
    unsigned long long mbar;
};

__global__ void __launch_bounds__(THREADS, 5)
fused_kernel(const float* __restrict__ X1, const float* __restrict__ X2,
             const int* __restrict__ m1, const int* __restrict__ m2,
             const int* __restrict__ mu, const float* __restrict__ mult,
             float* __restrict__ out, int nd2, int K)
{
    __shared__ Smem s;
    const int t = threadIdx.x;
    const int base2 = blockIdx.x * (TILE / 2);     // float2 index of tile start
    const uint32_t mbar_addr = (uint32_t)__cvta_generic_to_shared(&s.mbar);

    // ---- phase 0: mu to smem, mbarrier init -------------------------------
    if (t < K) s.rawmu[t] = mu[t];
    if (t == 0) {
        asm volatile("mbarrier.init.shared.b64 [%0], %1;"
                     :: "r"(mbar_addr), "r"(1) : "memory");
        asm volatile("fence.proxy.async.shared::cta;" ::: "memory");
    }
    __syncthreads();

    // ---- phase 1: TMA issue (t0) + mu histogram (t<=9) --------------------
    if (t == 0) {
        asm volatile("mbarrier.arrive.expect_tx.shared.b64 _, [%0], %1;"
                     :: "r"(mbar_addr), "r"((uint32_t)(2 * M_CH * TILE_B)) : "memory");
        uint32_t dst = (uint32_t)__cvta_generic_to_shared(&s.sx[0]);
        const char* src1 = (const char*)(X1 + (size_t)base2 * 2);
        const char* src2 = (const char*)(X2 + (size_t)base2 * 2);
        const size_t chanstride = (size_t)nd2 * 8;
#pragma unroll
        for (int m = 0; m < M_CH; m++) {
            asm volatile(
                "cp.async.bulk.shared::cta.global.mbarrier::complete_tx::bytes "
                "[%0], [%1], %2, [%3];"
                :: "r"(dst + m * TILE_B), "l"(src1 + m * chanstride),
                   "r"((uint32_t)TILE_B), "r"(mbar_addr) : "memory");
            asm volatile(
                "cp.async.bulk.shared::cta.global.mbarrier::complete_tx::bytes "
                "[%0], [%1], %2, [%3];"
                :: "r"(dst + (M_CH + m) * TILE_B), "l"(src2 + m * chanstride),
                   "r"((uint32_t)TILE_B), "r"(mbar_addr) : "memory");
        }
    }
    if (t <= M_CH) {                   // seg[m] = #{k : mu_k < m}  (mu sorted)
        int c = 0;
        for (int j = 0; j < K; j++) c += (s.rawmu[j] < t);
        s.seg[t] = c;
    }
    __syncthreads();

    // ---- phase 2a: padded segment starts + inert pads (t0) ----------------
    if (t == 0) {
        int p = 0;
        for (int m = 0; m < M_CH; m++) {
            s.pseg[m] = p;
            int len  = s.seg[m + 1] - s.seg[m];
            int plen = (len + 1) & ~1;                 // pad to multiple of 2
            if (plen != len)
                s.prog[p + len] = make_int2(0, 0);     // mult = 0 dummy
            p += plen;
        }
        s.pseg[M_CH] = p;
    }
    __syncthreads();

    // ---- phase 2b: scatter real terms (input order; mu sorted) ------------
    if (t < K) {
        const int m   = s.rawmu[t];
        const int pos = s.pseg[m] + (t - s.seg[m]);
        const int off1 = m1[t] * TILE_B;
        const int off2 = M_CH * TILE_B + m2[t] * TILE_B;
        s.prog[pos] = make_int2(off1 | (off2 << 16), __float_as_int(mult[t]));
    }
    __syncthreads();

    // ---- wait for TMA -----------------------------------------------------
    asm volatile(
        "{\n\t.reg .pred P;\n\t"
        "W_%=:\n\t"
        "mbarrier.try_wait.parity.acquire.cta.shared::cta.b64 P, [%0], 0, 0x989680;\n\t"
        "@P bra.uni D_%=;\n\t"
        "bra.uni W_%=;\n\t"
        "D_%=:\n\t}"
        :: "r"(mbar_addr) : "memory");

    // ---- main loop: flat unroll-2, float2 per thread ----------------------
    const uint32_t colb = (uint32_t)__cvta_generic_to_shared(&s.sx[0]) + t * 8;
    float2* __restrict__ out2 = (float2*)out;
    int kptr = 0;

#pragma unroll
    for (int m = 0; m < M_CH; m++) {
        unsigned long long acc = 0ull;
        const int k1 = s.pseg[m + 1];
        for (int k = kptr; k < k1; k += 2) {
            // one int4 broadcast = 2 terms
            int4 pr = *(const int4*)&s.prog[k];
#pragma unroll
            for (int u = 0; u < 2; u++) {
                const int pack = (u == 0) ? pr.x : pr.z;
                const int mlt  = (u == 0) ? pr.y : pr.w;
                unsigned long long a, b, c2;
                asm("ld.shared.b64 %0, [%1];"
                    : "=l"(a) : "r"(colb + (pack & 0xFFFF)));
                asm("ld.shared.b64 %0, [%1];"
                    : "=l"(b) : "r"(colb + ((unsigned)pack >> 16)));
                asm("mov.b64 %0, {%1, %1};" : "=l"(c2) : "r"(mlt));
                asm("mul.rn.f32x2 %0, %1, %2;" : "=l"(b) : "l"(c2), "l"(b));
                asm("fma.rn.f32x2 %0, %1, %2, %3;"
                    : "=l"(acc) : "l"(a), "l"(b), "l"(acc));
            }
        }
        kptr = k1;
        *(unsigned long long*)&out2[(size_t)m * nd2 + base2 + t] = acc;  // STG.64
    }
}

extern "C" void kernel_launch(void* const* d_in, const int* in_sizes, int n_in,
                              void* d_out, int out_size)
{
    const float* X1   = (const float*)d_in[0];
    const float* X2   = (const float*)d_in[1];
    const int*   m1   = (const int*)d_in[2];
    const int*   m2   = (const int*)d_in[3];
    const int*   mu   = (const int*)d_in[4];
    const float* mult = (const float*)d_in[5];
    float*       out  = (float*)d_out;

    const int K   = in_sizes[2];
    const int ND  = in_sizes[0] / M_CH;    // N*D
    const int nd2 = ND / 2;

    fused_kernel<<<ND / TILE, THREADS>>>(X1, X2, m1, m2, mu, mult, out, nd2, K);
}